// round 12
// baseline (speedup 1.0000x reference)
#include <cuda_runtime.h>

#define BB 2
#define NN 2048
#define CC 1024
#define HH 16
#define DD 64
#define NKC 16

typedef unsigned int u32;

// scratch (device globals: allocation-free)
__device__ float g_q[(size_t)BB*HH*NN*DD];
__device__ float g_k[(size_t)BB*HH*NN*DD];
__device__ float g_v[(size_t)BB*HH*NN*DD];
__device__ float g_a[(size_t)BB*NN*CC];

__device__ __forceinline__ u32 f2tf(float f) {
    u32 r; asm("cvt.rna.tf32.f32 %0, %1;" : "=r"(r) : "f"(f)); return r;
}

// D += A(16x8) * B(8x8), tf32 inputs, fp32 accum. sm_80 fragment layout:
// A: a0=(gid,t) a1=(gid+8,t) a2=(gid,t+4) a3=(gid+8,t+4); B: b0=(k=t,col gid) b1=(k=t+4,col gid)
// C: c0=(gid,2t) c1=(gid,2t+1) c2=(gid+8,2t) c3=(gid+8,2t+1)
__device__ __forceinline__ void mma8(float d[4], const u32 a[4], const u32 b[2]) {
    asm volatile(
        "mma.sync.aligned.m16n8k8.row.col.f32.tf32.tf32.f32 "
        "{%0,%1,%2,%3}, {%4,%5,%6,%7}, {%8,%9}, {%0,%1,%2,%3};"
        : "+f"(d[0]), "+f"(d[1]), "+f"(d[2]), "+f"(d[3])
        : "r"(a[0]), "r"(a[1]), "r"(a[2]), "r"(a[3]), "r"(b[0]), "r"(b[1]));
}

// ---------------------------------------------------------------------------
// GEMM: C[128x128] = A[128xCC] @ W[CCx128] tile. 8 warps (2m x 4n), warp 64x32,
// k-chunk 32, double-buffered frag-order smem.
// A frag-order: word = (rb*4+ks)*164 + gid*20 + t*4 + slot   (LDS.128 reads)
// B slot-major: word = ((ks*4+t)*2+slot)*132 + c             (STS.128 writes, LDS.32 reads)
// ---------------------------------------------------------------------------
#define GA_SZ 5248
#define GB_SZ 4224
#define G_SMEM_BYTES ((2 * (GA_SZ + GB_SZ)) * 4)   // 75776

__device__ __forceinline__ void gemm_stageA(u32* Ab, const float4& v, int idx) {
    int m = idx >> 3, k4 = (idx & 7) << 2;
    int ks = k4 >> 3, half = (k4 >> 2) & 1;
    int rb = m >> 4, r16 = m & 15, g = r16 & 7, rs = r16 >> 3;
    u32* p = Ab + (rb * 4 + ks) * 164 + g * 20 + half * 2 + rs;
    p[0] = f2tf(v.x); p[4] = f2tf(v.y); p[8] = f2tf(v.z); p[12] = f2tf(v.w);
}
__device__ __forceinline__ void gemm_stageB(u32* Bb, const float4& v, int idx) {
    int kk = idx >> 5, c4 = (idx & 31) << 2;
    int ks = kk >> 3, tk = kk & 7, t = tk & 3, sl = tk >> 2;
    *(uint4*)(Bb + ((ks * 4 + t) * 2 + sl) * 132 + c4) =
        make_uint4(f2tf(v.x), f2tf(v.y), f2tf(v.z), f2tf(v.w));
}

__device__ __forceinline__ void gemm_tc(const float* __restrict__ A,
                                        const float* __restrict__ W,
                                        u32* As, u32* Bs,
                                        float acc[4][4][4],
                                        int m0, int n0, int tid)
{
    const int lane = tid & 31, wid = tid >> 5;
    const int gid = lane >> 2, tg = lane & 3;
    const int wm = wid >> 2, wn = wid & 3;

    float4 pa[4], pb[4];
    #pragma unroll
    for (int i = 0; i < 4; i++) {
        int idx = tid + i * 256;
        pa[i] = *(const float4*)&A[(size_t)(m0 + (idx >> 3)) * CC + ((idx & 7) << 2)];
        pb[i] = *(const float4*)&W[(size_t)(idx >> 5) * CC + n0 + ((idx & 31) << 2)];
    }
    #pragma unroll
    for (int i = 0; i < 4; i++) {
        int idx = tid + i * 256;
        gemm_stageA(As, pa[i], idx);
        gemm_stageB(Bs, pb[i], idx);
    }
    __syncthreads();

    #pragma unroll 1
    for (int it = 0; it < CC / 32; ++it) {
        const int buf = it & 1;
        const u32* Ab = As + buf * GA_SZ;
        const u32* Bb = Bs + buf * GB_SZ;
        if (it + 1 < CC / 32) {
            int k0 = (it + 1) * 32;
            #pragma unroll
            for (int i = 0; i < 4; i++) {
                int idx = tid + i * 256;
                pa[i] = *(const float4*)&A[(size_t)(m0 + (idx >> 3)) * CC + k0 + ((idx & 7) << 2)];
                pb[i] = *(const float4*)&W[(size_t)(k0 + (idx >> 5)) * CC + n0 + ((idx & 31) << 2)];
            }
        }
        #pragma unroll
        for (int ks = 0; ks < 4; ++ks) {
            u32 af[4][4], bf[4][2];
            #pragma unroll
            for (int mt = 0; mt < 4; mt++) {
                uint4 a4 = *(const uint4*)(Ab + ((wm * 4 + mt) * 4 + ks) * 164 + gid * 20 + tg * 4);
                af[mt][0] = a4.x; af[mt][1] = a4.y; af[mt][2] = a4.z; af[mt][3] = a4.w;
            }
            const u32* brow = Bb + ((ks * 4 + tg) * 2) * 132;
            #pragma unroll
            for (int nt = 0; nt < 4; nt++) {
                int c = wn * 32 + nt * 8 + gid;
                bf[nt][0] = brow[c];
                bf[nt][1] = brow[132 + c];
            }
            #pragma unroll
            for (int mt = 0; mt < 4; mt++)
                #pragma unroll
                for (int nt = 0; nt < 4; nt++)
                    mma8(acc[mt][nt], af[mt], bf[nt]);
        }
        if (it + 1 < CC / 32) {
            u32* An = As + (buf ^ 1) * GA_SZ;
            u32* Bn = Bs + (buf ^ 1) * GB_SZ;
            #pragma unroll
            for (int i = 0; i < 4; i++) {
                int idx = tid + i * 256;
                gemm_stageA(An, pa[i], idx);
                gemm_stageB(Bn, pb[i], idx);
            }
        }
        __syncthreads();
    }
}

// ---------------------------------------------------------------------------
// QKV: q/k/v = x @ W{q,k,v}, scatter to [B,H,N,D]
// ---------------------------------------------------------------------------
__global__ void __launch_bounds__(256, 2) qkv_kernel(
    const float* __restrict__ x, const float* __restrict__ Wq,
    const float* __restrict__ Wk, const float* __restrict__ Wv)
{
    extern __shared__ u32 sm[];
    u32* As = sm;
    u32* Bs = sm + 2 * GA_SZ;

    const float* W; float* dst;
    if (blockIdx.z == 0)      { W = Wq; dst = g_q; }
    else if (blockIdx.z == 1) { W = Wk; dst = g_k; }
    else                      { W = Wv; dst = g_v; }

    const int tid = threadIdx.x;
    const int m0 = blockIdx.x * 128, n0 = blockIdx.y * 128;

    float acc[4][4][4] = {};
    gemm_tc(x, W, As, Bs, acc, m0, n0, tid);

    const int lane = tid & 31, wid = tid >> 5;
    const int gid = lane >> 2, tg = lane & 3;
    const int wm = wid >> 2, wn = wid & 3;
    #pragma unroll
    for (int mt = 0; mt < 4; mt++)
        #pragma unroll
        for (int h2 = 0; h2 < 2; h2++) {
            int m = m0 + wm * 64 + mt * 16 + h2 * 8 + gid;
            int b = m >> 11, n = m & (NN - 1);
            #pragma unroll
            for (int nt = 0; nt < 4; nt++) {
                int j = n0 + wn * 32 + nt * 8 + tg * 2;
                int head = j >> 6, d0 = j & 63;
                float2 v = h2 ? make_float2(acc[mt][nt][2], acc[mt][nt][3])
                              : make_float2(acc[mt][nt][0], acc[mt][nt][1]);
                *(float2*)&dst[((((size_t)b * HH + head) * NN + n) << 6) + d0] = v;
            }
        }
}

// ---------------------------------------------------------------------------
// Output projection: out = g_a @ Wp + bp
// ---------------------------------------------------------------------------
__global__ void __launch_bounds__(256, 2) proj_kernel(
    const float* __restrict__ Wp, const float* __restrict__ bp, float* __restrict__ outp)
{
    extern __shared__ u32 sm[];
    u32* As = sm;
    u32* Bs = sm + 2 * GA_SZ;

    const int tid = threadIdx.x;
    const int m0 = blockIdx.x * 128, n0 = blockIdx.y * 128;

    float acc[4][4][4] = {};
    gemm_tc(g_a, Wp, As, Bs, acc, m0, n0, tid);

    const int lane = tid & 31, wid = tid >> 5;
    const int gid = lane >> 2, tg = lane & 3;
    const int wm = wid >> 2, wn = wid & 3;
    #pragma unroll
    for (int mt = 0; mt < 4; mt++)
        #pragma unroll
        for (int h2 = 0; h2 < 2; h2++) {
            int m = m0 + wm * 64 + mt * 16 + h2 * 8 + gid;
            #pragma unroll
            for (int nt = 0; nt < 4; nt++) {
                int j = n0 + wn * 32 + nt * 8 + tg * 2;
                float2 bv = *(const float2*)&bp[j];
                float2 v = h2 ? make_float2(acc[mt][nt][2] + bv.x, acc[mt][nt][3] + bv.y)
                              : make_float2(acc[mt][nt][0] + bv.x, acc[mt][nt][1] + bv.y);
                *(float2*)&outp[(size_t)m * CC + j] = v;
            }
        }
}

// ---------------------------------------------------------------------------
// Attention v2: warp owns 16 full q-rows x 128 keys -> warp-local softmax
// (2 shfl_xor, no smem exchange). P warp-private. 2 syncthreads/chunk.
// smem (u32 words):
//   QF @ 0     : (w*8+ks)*164 + gid*20 + t*4 + slot            (8w x 8ks)  10496
//   KB @ 10496 : ((ks*4+t)*2+slot)*132 + key   (ks over d: 8)              8448
//   VB @ 18944 : ((ks2*4+t)*2+slot)*68 + d     (ks2 over key: 16)          8704
//   PF @ 27648 : w*2112 + ks2*132 + gid*16 + ((t^(gid&3))*4) + slot        16896
// ---------------------------------------------------------------------------
#define AT_QF 0
#define AT_KB 10496
#define AT_VB 18944
#define AT_PF 27648
#define A_SMEM_BYTES (44544 * 4)   // 178176

__global__ void __launch_bounds__(256) attn_kernel()
{
    extern __shared__ u32 sm[];
    u32* QF = sm + AT_QF;
    u32* KB = sm + AT_KB;
    u32* VB = sm + AT_VB;
    u32* PF = sm + AT_PF;

    const int tid = threadIdx.x;
    const int lane = tid & 31, w = tid >> 5;
    const int gid = lane >> 2, tg = lane & 3;
    const int qt = blockIdx.x, h = blockIdx.y, b = blockIdx.z;

    const size_t bh = (size_t)(b * HH + h) * NN * DD;
    const float* qg = g_q + bh + (size_t)qt * 128 * DD;
    const float* kg = g_k + bh;
    const float* vg = g_v + bh;

    // stage Q in A-frag order (scale folded)
    #pragma unroll
    for (int i = 0; i < 8; i++) {
        int idx = tid + i * 256;
        int row = idx >> 4, d4 = (idx & 15) << 2;
        float4 v = *(const float4*)&qg[row * 64 + d4];
        int ks = d4 >> 3, half = (d4 >> 2) & 1;
        int wq = row >> 4, r16 = row & 15, g = r16 & 7, rs = r16 >> 3;
        u32* p = QF + (wq * 8 + ks) * 164 + g * 20 + half * 2 + rs;
        p[0]  = f2tf(v.x * 0.125f); p[4]  = f2tf(v.y * 0.125f);
        p[8]  = f2tf(v.z * 0.125f); p[12] = f2tf(v.w * 0.125f);
    }

    float o[8][4] = {};
    const int xg = (gid & 3);   // P xor key
    const u32 pfw = w * 2112;

    #pragma unroll 1
    for (int kc = 0; kc < NKC; kc++) {
        __syncthreads();   // prev chunk reads done (and Q staged for kc=0)

        const float* kgc = kg + (size_t)kc * 128 * 64;
        const float* vgc = vg + (size_t)kc * 128 * 64;
        // stage K (B-side of MMA1, k=d): lanes span keys for bank spread
        #pragma unroll
        for (int i = 0; i < 8; i++) {
            int idx = tid + i * 256;
            int d4i = (idx & 3) | ((idx >> 9) << 2);
            int key = (idx >> 2) & 127;
            float4 v = *(const float4*)&kgc[key * 64 + d4i * 4];
            int ks = d4i >> 1, sl = d4i & 1;
            u32* p = KB + ((ks * 4) * 2 + sl) * 132 + key;
            p[0]     = f2tf(v.x);
            p[264]   = f2tf(v.y);
            p[528]   = f2tf(v.z);
            p[792]   = f2tf(v.w);
        }
        // stage V (B-side of MMA2, k=key): STS.128 along d
        #pragma unroll
        for (int i = 0; i < 8; i++) {
            int idx = tid + i * 256;
            int kk = idx >> 4, c4 = (idx & 15) << 2;
            float4 v = *(const float4*)&vgc[kk * 64 + c4];
            int ks2 = kk >> 3, tk = kk & 7, t = tk & 3, sl = tk >> 2;
            *(uint4*)(VB + ((ks2 * 4 + t) * 2 + sl) * 68 + c4) =
                make_uint4(f2tf(v.x), f2tf(v.y), f2tf(v.z), f2tf(v.w));
        }
        __syncthreads();

        // ---- MMA1: S(16q x 128key) = Q K^T, k over D=64 ----
        float s[16][4] = {};
        #pragma unroll
        for (int ks = 0; ks < 8; ks++) {
            uint4 a4 = *(const uint4*)(QF + (w * 8 + ks) * 164 + gid * 20 + tg * 4);
            u32 af[4] = { a4.x, a4.y, a4.z, a4.w };
            const u32* brow = KB + ((ks * 4 + tg) * 2) * 132;
            #pragma unroll
            for (int nt = 0; nt < 16; nt++) {
                u32 bf[2] = { brow[nt * 8 + gid], brow[132 + nt * 8 + gid] };
                mma8(s[nt], af, bf);
            }
        }

        // ---- warp-local softmax (rows gid and gid+8; quad covers all 128 cols) ----
        float m0 = -1e30f, m1 = -1e30f;
        #pragma unroll
        for (int nt = 0; nt < 16; nt++) {
            m0 = fmaxf(m0, fmaxf(s[nt][0], s[nt][1]));
            m1 = fmaxf(m1, fmaxf(s[nt][2], s[nt][3]));
        }
        m0 = fmaxf(m0, __shfl_xor_sync(0xffffffffu, m0, 1));
        m0 = fmaxf(m0, __shfl_xor_sync(0xffffffffu, m0, 2));
        m1 = fmaxf(m1, __shfl_xor_sync(0xffffffffu, m1, 1));
        m1 = fmaxf(m1, __shfl_xor_sync(0xffffffffu, m1, 2));
        float r0 = 0.f, r1 = 0.f;
        #pragma unroll
        for (int nt = 0; nt < 16; nt++) {
            s[nt][0] = __expf(s[nt][0] - m0); s[nt][1] = __expf(s[nt][1] - m0);
            s[nt][2] = __expf(s[nt][2] - m1); s[nt][3] = __expf(s[nt][3] - m1);
            r0 += s[nt][0] + s[nt][1];
            r1 += s[nt][2] + s[nt][3];
        }
        r0 += __shfl_xor_sync(0xffffffffu, r0, 1);
        r0 += __shfl_xor_sync(0xffffffffu, r0, 2);
        r1 += __shfl_xor_sync(0xffffffffu, r1, 1);
        r1 += __shfl_xor_sync(0xffffffffu, r1, 2);
        const float inv0 = 1.0f / r0, inv1 = 1.0f / r1;

        // ---- P -> warp-private frag-order smem ----
        {
            int cc0 = 2 * tg, cc1 = 2 * tg + 1;
            int t0 = cc0 & 3, hf0 = cc0 >> 2;
            int t1 = cc1 & 3, hf1 = cc1 >> 2;
            u32 base = pfw + gid * 16;
            u32 o00 = base + ((t0 ^ xg) << 2) + hf0 * 2;      // rows gid: slot hf*2+0
            u32 o01 = base + ((t1 ^ xg) << 2) + hf1 * 2;
            #pragma unroll
            for (int nt = 0; nt < 16; nt++) {
                u32 blk = nt * 132;
                PF[o00 + blk]     = f2tf(s[nt][0] * inv0);
                PF[o01 + blk]     = f2tf(s[nt][1] * inv0);
                PF[o00 + blk + 1] = f2tf(s[nt][2] * inv1);    // rows gid+8: slot hf*2+1
                PF[o01 + blk + 1] = f2tf(s[nt][3] * inv1);
            }
        }
        __syncwarp();

        // ---- MMA2: O(16q x 64d) += P V, k over 128 keys ----
        #pragma unroll
        for (int ks2 = 0; ks2 < 16; ks2++) {
            uint4 a4 = *(const uint4*)(PF + pfw + ks2 * 132 + gid * 16 + ((tg ^ xg) << 2));
            u32 af[4] = { a4.x, a4.y, a4.z, a4.w };
            const u32* brow = VB + ((ks2 * 4 + tg) * 2) * 68;
            #pragma unroll
            for (int nt = 0; nt < 8; nt++) {
                u32 bf[2] = { brow[nt * 8 + gid], brow[68 + nt * 8 + gid] };
                mma8(o[nt], af, bf);
            }
        }
    }

    // epilogue: rows w*16+gid(+8), cols d = nt*8 + 2tg(+1)
    const int n0r = qt * 128 + w * 16 + gid;
    float* p0 = &g_a[((size_t)b * NN + n0r) * CC + h * 64];
    float* p1 = &g_a[((size_t)b * NN + n0r + 8) * CC + h * 64];
    #pragma unroll
    for (int nt = 0; nt < 8; nt++) {
        int d0 = nt * 8 + tg * 2;
        *(float2*)&p0[d0] = make_float2(o[nt][0], o[nt][1]);
        *(float2*)&p1[d0] = make_float2(o[nt][2], o[nt][3]);
    }
}

// ---------------------------------------------------------------------------
extern "C" void kernel_launch(void* const* d_in, const int* in_sizes, int n_in,
                              void* d_out, int out_size)
{
    const float* x  = (const float*)d_in[0];
    const float* Wq = (const float*)d_in[1];
    const float* Wk = (const float*)d_in[2];
    const float* Wv = (const float*)d_in[3];
    const float* Wp = (const float*)d_in[4];
    const float* bp = (const float*)d_in[5];
    float* out = (float*)d_out;

    cudaFuncSetAttribute(qkv_kernel,  cudaFuncAttributeMaxDynamicSharedMemorySize, G_SMEM_BYTES);
    cudaFuncSetAttribute(proj_kernel, cudaFuncAttributeMaxDynamicSharedMemorySize, G_SMEM_BYTES);
    cudaFuncSetAttribute(attn_kernel, cudaFuncAttributeMaxDynamicSharedMemorySize, A_SMEM_BYTES);

    qkv_kernel<<<dim3(32, 8, 3), 256, G_SMEM_BYTES>>>(x, Wq, Wk, Wv);
    attn_kernel<<<dim3(16, 16, 2), 256, A_SMEM_BYTES>>>();
    proj_kernel<<<dim3(32, 8), 256, G_SMEM_BYTES>>>(Wp, bp, out);
}

// round 13
// speedup vs baseline: 1.1034x; 1.1034x over previous
#include <cuda_runtime.h>

#define BB 2
#define NN 2048
#define CC 1024
#define HH 16
#define DD 64
#define NKC 16

typedef unsigned int u32;

// scratch (device globals: allocation-free)
__device__ float g_q[(size_t)BB*HH*NN*DD];
__device__ float g_k[(size_t)BB*HH*NN*DD];
__device__ float g_v[(size_t)BB*HH*NN*DD];
__device__ float g_a[(size_t)BB*NN*CC];

__device__ __forceinline__ u32 f2tf(float f) {
    u32 r; asm("cvt.rna.tf32.f32 %0, %1;" : "=r"(r) : "f"(f)); return r;
}
__device__ __forceinline__ u32 cvta_sh(const void* p) {
    u32 a;
    asm("{ .reg .u64 t; cvta.to.shared.u64 t, %1; cvt.u32.u64 %0, t; }" : "=r"(a) : "l"(p));
    return a;
}
// ldmatrix x4: 4 tiles of 8 rows x 16B; lanes 8i..8i+7 supply row addrs of tile i.
// As tf32 (4 per row): reg i, lane j <- tile_i(row j>>2, col j&3).
__device__ __forceinline__ void ldsm4(u32 r[4], u32 addr) {
    asm volatile("ldmatrix.sync.aligned.m8n8.x4.shared.b16 {%0,%1,%2,%3}, [%4];"
        : "=r"(r[0]), "=r"(r[1]), "=r"(r[2]), "=r"(r[3]) : "r"(addr));
}
// D += A(16x8)*B(8x8), tf32, fp32 accum.
// A: a0=(gid,t) a1=(gid+8,t) a2=(gid,t+4) a3=(gid+8,t+4); B: b0=(k=t,col gid) b1=(k=t+4,col gid)
// C: c0=(gid,2t) c1=(gid,2t+1) c2=(gid+8,2t) c3=(gid+8,2t+1)
__device__ __forceinline__ void mma8(float d[4], const u32 a[4], const u32 b[2]) {
    asm volatile(
        "mma.sync.aligned.m16n8k8.row.col.f32.tf32.tf32.f32 "
        "{%0,%1,%2,%3}, {%4,%5,%6,%7}, {%8,%9}, {%0,%1,%2,%3};"
        : "+f"(d[0]), "+f"(d[1]), "+f"(d[2]), "+f"(d[3])
        : "r"(a[0]), "r"(a[1]), "r"(a[2]), "r"(a[3]), "r"(b[0]), "r"(b[1]));
}

// ---------------------------------------------------------------------------
// GEMM: C[128x128] = A[128xCC] @ W[CCx128]. 8 warps (2m x 4n), warp 64x32,
// k-chunk 32, double-buffered. A row-major [m][36] (ldmatrix A-frags),
// B row-major [k][132] (LDS.32 B-frags). All staging stores fused STS.128.
// ---------------------------------------------------------------------------
#define GA_STR 36
#define GB_STR 132
#define GA_SZ (128 * GA_STR)   // 4608 words
#define GB_SZ (32 * GB_STR)    // 4224 words
#define G_SMEM_BYTES ((2 * (GA_SZ + GB_SZ)) * 4)  // 70656

__device__ __forceinline__ void gemm_tc(const float* __restrict__ A,
                                        const float* __restrict__ W,
                                        u32* As, u32* Bs,
                                        float acc[4][4][4],
                                        int m0, int n0, int tid)
{
    const int lane = tid & 31, wid = tid >> 5;
    const int gid = lane >> 2, tg = lane & 3;
    const int wm = wid >> 2, wn = wid & 3;

    const u32 a_sh = cvta_sh(As);
    // ldmatrix lane address components (A pattern)
    const int arow = (lane & 7) + ((lane >> 3) & 1) * 8;
    const int akw  = (lane >> 4) * 4;
    u32 aoff[4];
    #pragma unroll
    for (int mt = 0; mt < 4; mt++)
        aoff[mt] = (u32)(((wm * 64 + mt * 16 + arow) * GA_STR + akw) * 4);

    float4 pa[4], pb[4];
    #pragma unroll
    for (int i = 0; i < 4; i++) {
        int idx = tid + i * 256;
        pa[i] = *(const float4*)&A[(size_t)(m0 + (idx >> 3)) * CC + ((idx & 7) << 2)];
        pb[i] = *(const float4*)&W[(size_t)(idx >> 5) * CC + n0 + ((idx & 31) << 2)];
    }
    #pragma unroll
    for (int i = 0; i < 4; i++) {
        int idx = tid + i * 256;
        u32* pA = &As[(idx >> 3) * GA_STR + ((idx & 7) << 2)];
        pA[0] = f2tf(pa[i].x); pA[1] = f2tf(pa[i].y); pA[2] = f2tf(pa[i].z); pA[3] = f2tf(pa[i].w);
        u32* pB = &Bs[(idx >> 5) * GB_STR + ((idx & 31) << 2)];
        pB[0] = f2tf(pb[i].x); pB[1] = f2tf(pb[i].y); pB[2] = f2tf(pb[i].z); pB[3] = f2tf(pb[i].w);
    }
    __syncthreads();

    #pragma unroll 1
    for (int it = 0; it < CC / 32; ++it) {
        const int buf = it & 1;
        const u32 abuf = a_sh + (u32)(buf * GA_SZ * 4);
        const u32* Bb = Bs + buf * GB_SZ;
        if (it + 1 < CC / 32) {
            int k0 = (it + 1) * 32;
            #pragma unroll
            for (int i = 0; i < 4; i++) {
                int idx = tid + i * 256;
                pa[i] = *(const float4*)&A[(size_t)(m0 + (idx >> 3)) * CC + k0 + ((idx & 7) << 2)];
                pb[i] = *(const float4*)&W[(size_t)(k0 + (idx >> 5)) * CC + n0 + ((idx & 31) << 2)];
            }
        }
        #pragma unroll
        for (int ks = 0; ks < 4; ++ks) {
            u32 af[4][4], bf[4][2];
            #pragma unroll
            for (int mt = 0; mt < 4; mt++)
                ldsm4(af[mt], abuf + aoff[mt] + ks * 32);
            const u32* brow0 = Bb + (ks * 8 + tg) * GB_STR;
            #pragma unroll
            for (int nt = 0; nt < 4; nt++) {
                int c = wn * 32 + nt * 8 + gid;
                bf[nt][0] = brow0[c];
                bf[nt][1] = brow0[4 * GB_STR + c];
            }
            #pragma unroll
            for (int mt = 0; mt < 4; mt++)
                #pragma unroll
                for (int nt = 0; nt < 4; nt++)
                    mma8(acc[mt][nt], af[mt], bf[nt]);
        }
        if (it + 1 < CC / 32) {
            u32* An = As + (buf ^ 1) * GA_SZ;
            u32* Bn = Bs + (buf ^ 1) * GB_SZ;
            #pragma unroll
            for (int i = 0; i < 4; i++) {
                int idx = tid + i * 256;
                u32* pA = &An[(idx >> 3) * GA_STR + ((idx & 7) << 2)];
                pA[0] = f2tf(pa[i].x); pA[1] = f2tf(pa[i].y); pA[2] = f2tf(pa[i].z); pA[3] = f2tf(pa[i].w);
                u32* pB = &Bn[(idx >> 5) * GB_STR + ((idx & 31) << 2)];
                pB[0] = f2tf(pb[i].x); pB[1] = f2tf(pb[i].y); pB[2] = f2tf(pb[i].z); pB[3] = f2tf(pb[i].w);
            }
        }
        __syncthreads();
    }
}

// ---------------------------------------------------------------------------
// QKV: q/k/v = x @ W{q,k,v}, scatter to [B,H,N,D]
// ---------------------------------------------------------------------------
__global__ void __launch_bounds__(256, 2) qkv_kernel(
    const float* __restrict__ x, const float* __restrict__ Wq,
    const float* __restrict__ Wk, const float* __restrict__ Wv)
{
    extern __shared__ u32 sm[];
    u32* As = sm;
    u32* Bs = sm + 2 * GA_SZ;

    const float* W; float* dst;
    if (blockIdx.z == 0)      { W = Wq; dst = g_q; }
    else if (blockIdx.z == 1) { W = Wk; dst = g_k; }
    else                      { W = Wv; dst = g_v; }

    const int tid = threadIdx.x;
    const int m0 = blockIdx.x * 128, n0 = blockIdx.y * 128;

    float acc[4][4][4] = {};
    gemm_tc(x, W, As, Bs, acc, m0, n0, tid);

    const int lane = tid & 31, wid = tid >> 5;
    const int gid = lane >> 2, tg = lane & 3;
    const int wm = wid >> 2, wn = wid & 3;
    #pragma unroll
    for (int mt = 0; mt < 4; mt++)
        #pragma unroll
        for (int h2 = 0; h2 < 2; h2++) {
            int m = m0 + wm * 64 + mt * 16 + h2 * 8 + gid;
            int b = m >> 11, n = m & (NN - 1);
            #pragma unroll
            for (int nt = 0; nt < 4; nt++) {
                int j = n0 + wn * 32 + nt * 8 + tg * 2;
                int head = j >> 6, d0 = j & 63;
                float2 v = h2 ? make_float2(acc[mt][nt][2], acc[mt][nt][3])
                              : make_float2(acc[mt][nt][0], acc[mt][nt][1]);
                *(float2*)&dst[((((size_t)b * HH + head) * NN + n) << 6) + d0] = v;
            }
        }
}

// ---------------------------------------------------------------------------
// Output projection: out = g_a @ Wp + bp
// ---------------------------------------------------------------------------
__global__ void __launch_bounds__(256, 2) proj_kernel(
    const float* __restrict__ Wp, const float* __restrict__ bp, float* __restrict__ outp)
{
    extern __shared__ u32 sm[];
    u32* As = sm;
    u32* Bs = sm + 2 * GA_SZ;

    const int tid = threadIdx.x;
    const int m0 = blockIdx.x * 128, n0 = blockIdx.y * 128;

    float acc[4][4][4] = {};
    gemm_tc(g_a, Wp, As, Bs, acc, m0, n0, tid);

    const int lane = tid & 31, wid = tid >> 5;
    const int gid = lane >> 2, tg = lane & 3;
    const int wm = wid >> 2, wn = wid & 3;
    #pragma unroll
    for (int mt = 0; mt < 4; mt++)
        #pragma unroll
        for (int h2 = 0; h2 < 2; h2++) {
            int m = m0 + wm * 64 + mt * 16 + h2 * 8 + gid;
            #pragma unroll
            for (int nt = 0; nt < 4; nt++) {
                int j = n0 + wn * 32 + nt * 8 + tg * 2;
                float2 bv = *(const float2*)&bp[j];
                float2 v = h2 ? make_float2(acc[mt][nt][2] + bv.x, acc[mt][nt][3] + bv.y)
                              : make_float2(acc[mt][nt][0] + bv.x, acc[mt][nt][1] + bv.y);
                *(float2*)&outp[(size_t)m * CC + j] = v;
            }
        }
}

// ---------------------------------------------------------------------------
// Attention: block = 128q x (b,h); warp owns 16 q-rows x all 128 keys
// (warp-local softmax, 0 cross-warp exchange). Q/K/V row-major pad 68
// (fused STS.128 staging + ldmatrix frag reads). P warp-private [16][132].
// 2 syncthreads per key chunk.
// ---------------------------------------------------------------------------
#define AQ_STR 68
#define AP_STR 132
#define AT_K (128 * AQ_STR)
#define AT_V (2 * 128 * AQ_STR)
#define AT_P (3 * 128 * AQ_STR)
#define A_WORDS (3 * 128 * AQ_STR + 8 * 16 * AP_STR)   // 26112 + 16896 = 43008
#define A_SMEM_BYTES (A_WORDS * 4)                     // 172032

__global__ void __launch_bounds__(256) attn_kernel()
{
    extern __shared__ u32 sm[];
    u32* Qs = sm;
    u32* Ks = sm + AT_K;
    u32* Vs = sm + AT_V;
    u32* Ps = sm + AT_P;

    const int tid = threadIdx.x;
    const int lane = tid & 31, w = tid >> 5;
    const int gid = lane >> 2, tg = lane & 3;
    const int qt = blockIdx.x, h = blockIdx.y, b = blockIdx.z;

    const size_t bh = (size_t)(b * HH + h) * NN * DD;
    const float* qg = g_q + bh + (size_t)qt * 128 * DD;
    const float* kg = g_k + bh;
    const float* vg = g_v + bh;

    const u32 sbase = cvta_sh(sm);
    // ldmatrix lane addresses
    const int lrow = (lane & 7) + ((lane >> 3) & 1) * 8;   // A-pattern row-in-16
    const int lkw  = (lane >> 4) * 4;                      // A-pattern k-word
    const u32 qaddr = sbase + (u32)(((w * 16 + lrow) * AQ_STR + lkw) * 4);
    // K B-pattern: lane j -> key (j>>4)*8 + (j&7), k-word ((j>>3)&1)*4
    const int krow = ((lane >> 4) << 3) + (lane & 7);
    const int kkw  = ((lane >> 3) & 1) * 4;
    const u32 kaddr = sbase + (u32)((AT_K + krow * AQ_STR + kkw) * 4);
    const u32 paddr = sbase + (u32)((AT_P + w * 16 * AP_STR + lrow * AP_STR + lkw) * 4);
    u32* Pw = Ps + w * 16 * AP_STR;

    // stage Q (scale folded), fused STS.128
    #pragma unroll
    for (int i = 0; i < 8; i++) {
        int idx = tid + i * 256;
        int r = idx >> 4, c4 = (idx & 15) << 2;
        float4 v = *(const float4*)&qg[r * 64 + c4];
        u32* p = &Qs[r * AQ_STR + c4];
        p[0] = f2tf(v.x * 0.125f); p[1] = f2tf(v.y * 0.125f);
        p[2] = f2tf(v.z * 0.125f); p[3] = f2tf(v.w * 0.125f);
    }

    float o[8][4] = {};

    #pragma unroll 1
    for (int kc = 0; kc < NKC; kc++) {
        __syncthreads();   // prev chunk reads of Ks/Vs done (Q covered by stage sync below)

        const float* kgc = kg + (size_t)kc * 128 * 64;
        const float* vgc = vg + (size_t)kc * 128 * 64;
        #pragma unroll
        for (int i = 0; i < 8; i++) {
            int idx = tid + i * 256;
            int r = idx >> 4, c4 = (idx & 15) << 2;
            float4 kv = *(const float4*)&kgc[r * 64 + c4];
            float4 vv = *(const float4*)&vgc[r * 64 + c4];
            u32* pk = &Ks[r * AQ_STR + c4];
            pk[0] = f2tf(kv.x); pk[1] = f2tf(kv.y); pk[2] = f2tf(kv.z); pk[3] = f2tf(kv.w);
            u32* pv = &Vs[r * AQ_STR + c4];
            pv[0] = f2tf(vv.x); pv[1] = f2tf(vv.y); pv[2] = f2tf(vv.z); pv[3] = f2tf(vv.w);
        }
        __syncthreads();

        // ---- MMA1: S(16q x 128key) = Q K^T, k over D=64; all frags via ldmatrix ----
        float s[16][4] = {};
        #pragma unroll
        for (int ks = 0; ks < 8; ks++) {
            u32 qa[4];
            ldsm4(qa, qaddr + ks * 32);
            #pragma unroll
            for (int g2 = 0; g2 < 8; g2++) {      // 16 keys per ldmatrix
                u32 kb[4];
                ldsm4(kb, kaddr + (u32)(g2 * 16 * AQ_STR * 4) + ks * 32);
                mma8(s[g2 * 2],     qa, kb);
                mma8(s[g2 * 2 + 1], qa, kb + 2);
            }
        }

        // ---- warp-local softmax (rows gid and gid+8 over all 128 cols) ----
        float m0 = -1e30f, m1 = -1e30f;
        #pragma unroll
        for (int nt = 0; nt < 16; nt++) {
            m0 = fmaxf(m0, fmaxf(s[nt][0], s[nt][1]));
            m1 = fmaxf(m1, fmaxf(s[nt][2], s[nt][3]));
        }
        m0 = fmaxf(m0, __shfl_xor_sync(0xffffffffu, m0, 1));
        m0 = fmaxf(m0, __shfl_xor_sync(0xffffffffu, m0, 2));
        m1 = fmaxf(m1, __shfl_xor_sync(0xffffffffu, m1, 1));
        m1 = fmaxf(m1, __shfl_xor_sync(0xffffffffu, m1, 2));
        float r0 = 0.f, r1 = 0.f;
        #pragma unroll
        for (int nt = 0; nt < 16; nt++) {
            s[nt][0] = __expf(s[nt][0] - m0); s[nt][1] = __expf(s[nt][1] - m0);
            s[nt][2] = __expf(s[nt][2] - m1); s[nt][3] = __expf(s[nt][3] - m1);
            r0 += s[nt][0] + s[nt][1];
            r1 += s[nt][2] + s[nt][3];
        }
        r0 += __shfl_xor_sync(0xffffffffu, r0, 1);
        r0 += __shfl_xor_sync(0xffffffffu, r0, 2);
        r1 += __shfl_xor_sync(0xffffffffu, r1, 1);
        r1 += __shfl_xor_sync(0xffffffffu, r1, 2);
        const float inv0 = 1.0f / r0, inv1 = 1.0f / r1;

        // ---- P -> warp-private smem, row-major [16][132], fused STS.64 ----
        #pragma unroll
        for (int nt = 0; nt < 16; nt++) {
            int c = nt * 8 + tg * 2;
            *(uint2*)&Pw[gid * AP_STR + c] =
                make_uint2(f2tf(s[nt][0] * inv0), f2tf(s[nt][1] * inv0));
            *(uint2*)&Pw[(gid + 8) * AP_STR + c] =
                make_uint2(f2tf(s[nt][2] * inv1), f2tf(s[nt][3] * inv1));
        }
        __syncwarp();

        // ---- MMA2: O(16q x 64d) += P V, k over 128 keys; P via ldmatrix ----
        #pragma unroll
        for (int ks2 = 0; ks2 < 16; ks2++) {
            u32 pa[4];
            ldsm4(pa, paddr + ks2 * 32);
            const u32* vrow = &Vs[(ks2 * 8 + tg) * AQ_STR];
            #pragma unroll
            for (int nt = 0; nt < 8; nt++) {
                u32 bf[2] = { vrow[nt * 8 + gid], vrow[4 * AQ_STR + nt * 8 + gid] };
                mma8(o[nt], pa, bf);
            }
        }
    }

    // epilogue: rows w*16+gid(+8), cols d = nt*8 + 2tg(+1)
    const int n0r = qt * 128 + w * 16 + gid;
    float* p0 = &g_a[((size_t)b * NN + n0r) * CC + h * 64];
    float* p1 = &g_a[((size_t)b * NN + n0r + 8) * CC + h * 64];
    #pragma unroll
    for (int nt = 0; nt < 8; nt++) {
        int d0 = nt * 8 + tg * 2;
        *(float2*)&p0[d0] = make_float2(o[nt][0], o[nt][1]);
        *(float2*)&p1[d0] = make_float2(o[nt][2], o[nt][3]);
    }
}

// ---------------------------------------------------------------------------
extern "C" void kernel_launch(void* const* d_in, const int* in_sizes, int n_in,
                              void* d_out, int out_size)
{
    const float* x  = (const float*)d_in[0];
    const float* Wq = (const float*)d_in[1];
    const float* Wk = (const float*)d_in[2];
    const float* Wv = (const float*)d_in[3];
    const float* Wp = (const float*)d_in[4];
    const float* bp = (const float*)d_in[5];
    float* out = (float*)d_out;

    cudaFuncSetAttribute(qkv_kernel,  cudaFuncAttributeMaxDynamicSharedMemorySize, G_SMEM_BYTES);
    cudaFuncSetAttribute(proj_kernel, cudaFuncAttributeMaxDynamicSharedMemorySize, G_SMEM_BYTES);
    cudaFuncSetAttribute(attn_kernel, cudaFuncAttributeMaxDynamicSharedMemorySize, A_SMEM_BYTES);

    qkv_kernel<<<dim3(32, 8, 3), 256, G_SMEM_BYTES>>>(x, Wq, Wk, Wv);
    attn_kernel<<<dim3(16, 16, 2), 256, A_SMEM_BYTES>>>();
    proj_kernel<<<dim3(32, 8), 256, G_SMEM_BYTES>>>(Wp, bp, out);
}

// round 14
// speedup vs baseline: 1.1252x; 1.0197x over previous
#include <cuda_runtime.h>

#define BB 2
#define NN 2048
#define CC 1024
#define HH 16
#define DD 64
#define NKC 16

typedef unsigned int u32;

// scratch (device globals: allocation-free). All tf32 bit patterns stored as u32.
__device__ u32 g_xt[(size_t)BB*NN*CC];
__device__ u32 g_wt[4][(size_t)CC*CC];
__device__ u32 g_q[(size_t)BB*HH*NN*DD];
__device__ u32 g_k[(size_t)BB*HH*NN*DD];
__device__ u32 g_v[(size_t)BB*HH*NN*DD];
__device__ u32 g_a[(size_t)BB*NN*CC];

__device__ __forceinline__ u32 f2tf(float f) {
    u32 r; asm("cvt.rna.tf32.f32 %0, %1;" : "=r"(r) : "f"(f)); return r;
}
__device__ __forceinline__ u32 cvta_sh(const void* p) {
    u32 a;
    asm("{ .reg .u64 t; cvta.to.shared.u64 t, %1; cvt.u32.u64 %0, t; }" : "=r"(a) : "l"(p));
    return a;
}
// ldmatrix x4: 4 tiles of 8 rows x 16B; lanes 8i..8i+7 supply row addrs of tile i.
__device__ __forceinline__ void ldsm4(u32 r[4], u32 addr) {
    asm volatile("ldmatrix.sync.aligned.m8n8.x4.shared.b16 {%0,%1,%2,%3}, [%4];"
        : "=r"(r[0]), "=r"(r[1]), "=r"(r[2]), "=r"(r[3]) : "r"(addr));
}
// D += A(16x8)*B(8x8), tf32, fp32 accum.
__device__ __forceinline__ void mma8(float d[4], const u32 a[4], const u32 b[2]) {
    asm volatile(
        "mma.sync.aligned.m16n8k8.row.col.f32.tf32.tf32.f32 "
        "{%0,%1,%2,%3}, {%4,%5,%6,%7}, {%8,%9}, {%0,%1,%2,%3};"
        : "+f"(d[0]), "+f"(d[1]), "+f"(d[2]), "+f"(d[3])
        : "r"(a[0]), "r"(a[1]), "r"(a[2]), "r"(a[3]), "r"(b[0]), "r"(b[1]));
}

// ---------------------------------------------------------------------------
// Pre-pass: convert x and the four weight matrices to tf32 bits (once).
// ---------------------------------------------------------------------------
__global__ void __launch_bounds__(256) cvt_kernel(
    const float* __restrict__ x,  const float* __restrict__ Wq,
    const float* __restrict__ Wk, const float* __restrict__ Wv,
    const float* __restrict__ Wp)
{
    const int seg = blockIdx.y;
    const float* src; u32* dst; int n;
    if (seg == 0)      { src = x;  dst = g_xt;    n = BB * NN * CC; }
    else               { src = (seg == 1) ? Wq : (seg == 2) ? Wk : (seg == 3) ? Wv : Wp;
                         dst = g_wt[seg - 1];     n = CC * CC; }
    int i = (blockIdx.x * 256 + threadIdx.x) * 4;
    if (i < n) {
        float4 v = *(const float4*)&src[i];
        *(uint4*)&dst[i] = make_uint4(f2tf(v.x), f2tf(v.y), f2tf(v.z), f2tf(v.w));
    }
}

// ---------------------------------------------------------------------------
// GEMM: C[128x128] = A[128xCC] @ W[CCx128]. 8 warps (2m x 4n), warp 64x32,
// k-chunk 32, double-buffered. Staging is a pure uint4 copy (no cvt).
// A row-major [m][36] (ldmatrix A-frags), B row-major [k][132] (LDS.32).
// ---------------------------------------------------------------------------
#define GA_STR 36
#define GB_STR 132
#define GA_SZ (128 * GA_STR)
#define GB_SZ (32 * GB_STR)
#define G_SMEM_BYTES ((2 * (GA_SZ + GB_SZ)) * 4)  // 70656

__device__ __forceinline__ void gemm_tc(const u32* __restrict__ A,
                                        const u32* __restrict__ W,
                                        u32* As, u32* Bs,
                                        float acc[4][4][4],
                                        int m0, int n0, int tid)
{
    const int lane = tid & 31, wid = tid >> 5;
    const int gid = lane >> 2, tg = lane & 3;
    const int wm = wid >> 2, wn = wid & 3;

    const u32 a_sh = cvta_sh(As);
    const int arow = (lane & 7) + ((lane >> 3) & 1) * 8;
    const int akw  = (lane >> 4) * 4;
    u32 aoff[4];
    #pragma unroll
    for (int mt = 0; mt < 4; mt++)
        aoff[mt] = (u32)(((wm * 64 + mt * 16 + arow) * GA_STR + akw) * 4);

    uint4 pa[4], pb[4];
    #pragma unroll
    for (int i = 0; i < 4; i++) {
        int idx = tid + i * 256;
        pa[i] = *(const uint4*)&A[(size_t)(m0 + (idx >> 3)) * CC + ((idx & 7) << 2)];
        pb[i] = *(const uint4*)&W[(size_t)(idx >> 5) * CC + n0 + ((idx & 31) << 2)];
    }
    #pragma unroll
    for (int i = 0; i < 4; i++) {
        int idx = tid + i * 256;
        *(uint4*)&As[(idx >> 3) * GA_STR + ((idx & 7) << 2)] = pa[i];
        *(uint4*)&Bs[(idx >> 5) * GB_STR + ((idx & 31) << 2)] = pb[i];
    }
    __syncthreads();

    #pragma unroll 1
    for (int it = 0; it < CC / 32; ++it) {
        const int buf = it & 1;
        const u32 abuf = a_sh + (u32)(buf * GA_SZ * 4);
        const u32* Bb = Bs + buf * GB_SZ;
        if (it + 1 < CC / 32) {
            int k0 = (it + 1) * 32;
            #pragma unroll
            for (int i = 0; i < 4; i++) {
                int idx = tid + i * 256;
                pa[i] = *(const uint4*)&A[(size_t)(m0 + (idx >> 3)) * CC + k0 + ((idx & 7) << 2)];
                pb[i] = *(const uint4*)&W[(size_t)(k0 + (idx >> 5)) * CC + n0 + ((idx & 31) << 2)];
            }
        }
        #pragma unroll
        for (int ks = 0; ks < 4; ++ks) {
            u32 af[4][4], bf[4][2];
            #pragma unroll
            for (int mt = 0; mt < 4; mt++)
                ldsm4(af[mt], abuf + aoff[mt] + ks * 32);
            const u32* brow0 = Bb + (ks * 8 + tg) * GB_STR;
            #pragma unroll
            for (int nt = 0; nt < 4; nt++) {
                int c = wn * 32 + nt * 8 + gid;
                bf[nt][0] = brow0[c];
                bf[nt][1] = brow0[4 * GB_STR + c];
            }
            #pragma unroll
            for (int mt = 0; mt < 4; mt++)
                #pragma unroll
                for (int nt = 0; nt < 4; nt++)
                    mma8(acc[mt][nt], af[mt], bf[nt]);
        }
        if (it + 1 < CC / 32) {
            u32* An = As + (buf ^ 1) * GA_SZ;
            u32* Bn = Bs + (buf ^ 1) * GB_SZ;
            #pragma unroll
            for (int i = 0; i < 4; i++) {
                int idx = tid + i * 256;
                *(uint4*)&An[(idx >> 3) * GA_STR + ((idx & 7) << 2)] = pa[i];
                *(uint4*)&Bn[(idx >> 5) * GB_STR + ((idx & 31) << 2)] = pb[i];
            }
        }
        __syncthreads();
    }
}

// ---------------------------------------------------------------------------
// QKV: q/k/v = x @ W{q,k,v}; epilogue stores tf32 bits (q pre-scaled by 1/8)
// ---------------------------------------------------------------------------
__global__ void __launch_bounds__(256, 2) qkv_kernel()
{
    extern __shared__ u32 sm[];
    u32* As = sm;
    u32* Bs = sm + 2 * GA_SZ;

    u32* dst;
    float sc;
    if (blockIdx.z == 0)      { dst = g_q; sc = 0.125f; }
    else if (blockIdx.z == 1) { dst = g_k; sc = 1.0f; }
    else                      { dst = g_v; sc = 1.0f; }
    const u32* W = g_wt[blockIdx.z];

    const int tid = threadIdx.x;
    const int m0 = blockIdx.x * 128, n0 = blockIdx.y * 128;

    float acc[4][4][4] = {};
    gemm_tc(g_xt, W, As, Bs, acc, m0, n0, tid);

    const int lane = tid & 31, wid = tid >> 5;
    const int gid = lane >> 2, tg = lane & 3;
    const int wm = wid >> 2, wn = wid & 3;
    #pragma unroll
    for (int mt = 0; mt < 4; mt++)
        #pragma unroll
        for (int h2 = 0; h2 < 2; h2++) {
            int m = m0 + wm * 64 + mt * 16 + h2 * 8 + gid;
            int b = m >> 11, n = m & (NN - 1);
            #pragma unroll
            for (int nt = 0; nt < 4; nt++) {
                int j = n0 + wn * 32 + nt * 8 + tg * 2;
                int head = j >> 6, d0 = j & 63;
                uint2 v = h2 ? make_uint2(f2tf(acc[mt][nt][2] * sc), f2tf(acc[mt][nt][3] * sc))
                             : make_uint2(f2tf(acc[mt][nt][0] * sc), f2tf(acc[mt][nt][1] * sc));
                *(uint2*)&dst[((((size_t)b * HH + head) * NN + n) << 6) + d0] = v;
            }
        }
}

// ---------------------------------------------------------------------------
// Output projection: out = g_a @ Wp + bp
// ---------------------------------------------------------------------------
__global__ void __launch_bounds__(256, 2) proj_kernel(
    const float* __restrict__ bp, float* __restrict__ outp)
{
    extern __shared__ u32 sm[];
    u32* As = sm;
    u32* Bs = sm + 2 * GA_SZ;

    const int tid = threadIdx.x;
    const int m0 = blockIdx.x * 128, n0 = blockIdx.y * 128;

    float acc[4][4][4] = {};
    gemm_tc(g_a, g_wt[3], As, Bs, acc, m0, n0, tid);

    const int lane = tid & 31, wid = tid >> 5;
    const int gid = lane >> 2, tg = lane & 3;
    const int wm = wid >> 2, wn = wid & 3;
    #pragma unroll
    for (int mt = 0; mt < 4; mt++)
        #pragma unroll
        for (int h2 = 0; h2 < 2; h2++) {
            int m = m0 + wm * 64 + mt * 16 + h2 * 8 + gid;
            #pragma unroll
            for (int nt = 0; nt < 4; nt++) {
                int j = n0 + wn * 32 + nt * 8 + tg * 2;
                float2 bv = *(const float2*)&bp[j];
                float2 v = h2 ? make_float2(acc[mt][nt][2] + bv.x, acc[mt][nt][3] + bv.y)
                              : make_float2(acc[mt][nt][0] + bv.x, acc[mt][nt][1] + bv.y);
                *(float2*)&outp[(size_t)m * CC + j] = v;
            }
        }
}

// ---------------------------------------------------------------------------
// Attention: block = 128q x (b,h); warp owns 16 q-rows x all 128 keys.
// Q/K/V arrive as tf32 bits -> staging is a pure uint4 copy.
// ---------------------------------------------------------------------------
#define AQ_STR 68
#define AP_STR 132
#define AT_K (128 * AQ_STR)
#define AT_V (2 * 128 * AQ_STR)
#define AT_P (3 * 128 * AQ_STR)
#define A_WORDS (3 * 128 * AQ_STR + 8 * 16 * AP_STR)
#define A_SMEM_BYTES (A_WORDS * 4)   // 172032

__global__ void __launch_bounds__(256) attn_kernel()
{
    extern __shared__ u32 sm[];
    u32* Qs = sm;
    u32* Ks = sm + AT_K;
    u32* Vs = sm + AT_V;
    u32* Ps = sm + AT_P;

    const int tid = threadIdx.x;
    const int lane = tid & 31, w = tid >> 5;
    const int gid = lane >> 2, tg = lane & 3;
    const int qt = blockIdx.x, h = blockIdx.y, b = blockIdx.z;

    const size_t bh = (size_t)(b * HH + h) * NN * DD;
    const u32* qg = g_q + bh + (size_t)qt * 128 * DD;
    const u32* kg = g_k + bh;
    const u32* vg = g_v + bh;

    const u32 sbase = cvta_sh(sm);
    const int lrow = (lane & 7) + ((lane >> 3) & 1) * 8;
    const int lkw  = (lane >> 4) * 4;
    const u32 qaddr = sbase + (u32)(((w * 16 + lrow) * AQ_STR + lkw) * 4);
    const int krow = ((lane >> 4) << 3) + (lane & 7);
    const int kkw  = ((lane >> 3) & 1) * 4;
    const u32 kaddr = sbase + (u32)((AT_K + krow * AQ_STR + kkw) * 4);
    const u32 paddr = sbase + (u32)((AT_P + w * 16 * AP_STR + lrow * AP_STR + lkw) * 4);
    u32* Pw = Ps + w * 16 * AP_STR;

    // stage Q: pure copy (scale already folded at qkv epilogue)
    #pragma unroll
    for (int i = 0; i < 8; i++) {
        int idx = tid + i * 256;
        int r = idx >> 4, c4 = (idx & 15) << 2;
        *(uint4*)&Qs[r * AQ_STR + c4] = *(const uint4*)&qg[r * 64 + c4];
    }

    float o[8][4] = {};

    #pragma unroll 1
    for (int kc = 0; kc < NKC; kc++) {
        __syncthreads();

        const u32* kgc = kg + (size_t)kc * 128 * 64;
        const u32* vgc = vg + (size_t)kc * 128 * 64;
        #pragma unroll
        for (int i = 0; i < 8; i++) {
            int idx = tid + i * 256;
            int r = idx >> 4, c4 = (idx & 15) << 2;
            *(uint4*)&Ks[r * AQ_STR + c4] = *(const uint4*)&kgc[r * 64 + c4];
            *(uint4*)&Vs[r * AQ_STR + c4] = *(const uint4*)&vgc[r * 64 + c4];
        }
        __syncthreads();

        // ---- MMA1: S(16q x 128key) = Q K^T, k over D=64 ----
        float s[16][4] = {};
        #pragma unroll
        for (int ks = 0; ks < 8; ks++) {
            u32 qa[4];
            ldsm4(qa, qaddr + ks * 32);
            #pragma unroll
            for (int g2 = 0; g2 < 8; g2++) {
                u32 kb[4];
                ldsm4(kb, kaddr + (u32)(g2 * 16 * AQ_STR * 4) + ks * 32);
                mma8(s[g2 * 2],     qa, kb);
                mma8(s[g2 * 2 + 1], qa, kb + 2);
            }
        }

        // ---- warp-local softmax (rows gid and gid+8 over 128 cols) ----
        float m0 = -1e30f, m1 = -1e30f;
        #pragma unroll
        for (int nt = 0; nt < 16; nt++) {
            m0 = fmaxf(m0, fmaxf(s[nt][0], s[nt][1]));
            m1 = fmaxf(m1, fmaxf(s[nt][2], s[nt][3]));
        }
        m0 = fmaxf(m0, __shfl_xor_sync(0xffffffffu, m0, 1));
        m0 = fmaxf(m0, __shfl_xor_sync(0xffffffffu, m0, 2));
        m1 = fmaxf(m1, __shfl_xor_sync(0xffffffffu, m1, 1));
        m1 = fmaxf(m1, __shfl_xor_sync(0xffffffffu, m1, 2));
        float r0 = 0.f, r1 = 0.f;
        #pragma unroll
        for (int nt = 0; nt < 16; nt++) {
            s[nt][0] = __expf(s[nt][0] - m0); s[nt][1] = __expf(s[nt][1] - m0);
            s[nt][2] = __expf(s[nt][2] - m1); s[nt][3] = __expf(s[nt][3] - m1);
            r0 += s[nt][0] + s[nt][1];
            r1 += s[nt][2] + s[nt][3];
        }
        r0 += __shfl_xor_sync(0xffffffffu, r0, 1);
        r0 += __shfl_xor_sync(0xffffffffu, r0, 2);
        r1 += __shfl_xor_sync(0xffffffffu, r1, 1);
        r1 += __shfl_xor_sync(0xffffffffu, r1, 2);
        const float inv0 = 1.0f / r0, inv1 = 1.0f / r1;

        // ---- P -> warp-private smem (the one remaining cvt site) ----
        #pragma unroll
        for (int nt = 0; nt < 16; nt++) {
            int c = nt * 8 + tg * 2;
            *(uint2*)&Pw[gid * AP_STR + c] =
                make_uint2(f2tf(s[nt][0] * inv0), f2tf(s[nt][1] * inv0));
            *(uint2*)&Pw[(gid + 8) * AP_STR + c] =
                make_uint2(f2tf(s[nt][2] * inv1), f2tf(s[nt][3] * inv1));
        }
        __syncwarp();

        // ---- MMA2: O(16q x 64d) += P V, k over 128 keys ----
        #pragma unroll
        for (int ks2 = 0; ks2 < 16; ks2++) {
            u32 pa[4];
            ldsm4(pa, paddr + ks2 * 32);
            const u32* vrow = &Vs[(ks2 * 8 + tg) * AQ_STR];
            #pragma unroll
            for (int nt = 0; nt < 8; nt++) {
                u32 bf[2] = { vrow[nt * 8 + gid], vrow[4 * AQ_STR + nt * 8 + gid] };
                mma8(o[nt], pa, bf);
            }
        }
    }

    // epilogue: store O as tf32 bits into g_a (proj consumes tf32)
    const int n0r = qt * 128 + w * 16 + gid;
    u32* p0 = &g_a[((size_t)b * NN + n0r) * CC + h * 64];
    u32* p1 = &g_a[((size_t)b * NN + n0r + 8) * CC + h * 64];
    #pragma unroll
    for (int nt = 0; nt < 8; nt++) {
        int d0 = nt * 8 + tg * 2;
        *(uint2*)&p0[d0] = make_uint2(f2tf(o[nt][0]), f2tf(o[nt][1]));
        *(uint2*)&p1[d0] = make_uint2(f2tf(o[nt][2]), f2tf(o[nt][3]));
    }
}

// ---------------------------------------------------------------------------
extern "C" void kernel_launch(void* const* d_in, const int* in_sizes, int n_in,
                              void* d_out, int out_size)
{
    const float* x  = (const float*)d_in[0];
    const float* Wq = (const float*)d_in[1];
    const float* Wk = (const float*)d_in[2];
    const float* Wv = (const float*)d_in[3];
    const float* Wp = (const float*)d_in[4];
    const float* bp = (const float*)d_in[5];
    float* out = (float*)d_out;

    cudaFuncSetAttribute(qkv_kernel,  cudaFuncAttributeMaxDynamicSharedMemorySize, G_SMEM_BYTES);
    cudaFuncSetAttribute(proj_kernel, cudaFuncAttributeMaxDynamicSharedMemorySize, G_SMEM_BYTES);
    cudaFuncSetAttribute(attn_kernel, cudaFuncAttributeMaxDynamicSharedMemorySize, A_SMEM_BYTES);

    cvt_kernel<<<dim3(4096, 5), 256>>>(x, Wq, Wk, Wv, Wp);
    qkv_kernel<<<dim3(32, 8, 3), 256, G_SMEM_BYTES>>>();
    attn_kernel<<<dim3(16, 16, 2), 256, A_SMEM_BYTES>>>();
    proj_kernel<<<dim3(32, 8), 256, G_SMEM_BYTES>>>(bp, out);
}